// round 13
// baseline (speedup 1.0000x reference)
#include <cuda_runtime.h>
#include <cuda_fp16.h>
#include <cstdint>
#include <math.h>

// Problem constants
#define BB   8
#define HH   128
#define WW   128
#define CIN  64
#define GG   2
#define GCH  32      // channels per group
#define SCH  288     // K*K*GC
#define GF   64      // filters per group
#define NP   (BB*HH*WW)   // 131072 pixels

// Scratch
__device__ __half g_samp16[(size_t)GG * NP * SCH]; // sampled field (151 MB)
__device__ float  g_off [(size_t)GG * NP * 18];    // offsets       (19 MB)
__device__ float  g_pww [(size_t)GG * SCH * GF];   // tf32-rounded pw weights

// ---------------------------------------------------------------------------
// helpers
// ---------------------------------------------------------------------------
__device__ __forceinline__ void cpa16(void* s, const void* gsrc, bool v) {
    unsigned int sa = (unsigned int)__cvta_generic_to_shared(s);
    asm volatile("cp.async.cg.shared.global [%0], [%1], 16, %2;"
                 :: "r"(sa), "l"(gsrc), "r"(v ? 16u : 0u));
}
#define CPA_COMMIT() asm volatile("cp.async.commit_group;")
#define CPA_WAIT0()  asm volatile("cp.async.wait_group 0;")

__device__ __forceinline__ float to_tf32(float x) {
    unsigned int u;
    asm("cvt.rna.tf32.f32 %0, %1;" : "=r"(u) : "f"(x));
    return __uint_as_float(u);
}

__device__ __forceinline__ void mma_tf32(float* d,
    unsigned int a0, unsigned int a1, unsigned int a2, unsigned int a3,
    unsigned int b0, unsigned int b1)
{
    asm volatile(
        "mma.sync.aligned.m16n8k8.row.col.f32.tf32.tf32.f32 "
        "{%0,%1,%2,%3}, {%4,%5,%6,%7}, {%8,%9}, {%0,%1,%2,%3};"
        : "+f"(d[0]), "+f"(d[1]), "+f"(d[2]), "+f"(d[3])
        : "r"(a0), "r"(a1), "r"(a2), "r"(a3), "r"(b0), "r"(b1));
}

// ===========================================================================
// Kernel P: pre-round pw weights to tf32 (once, tiny)
// ===========================================================================
__global__ void k_prep(const float* __restrict__ pw_w) {
    int i = blockIdx.x * 256 + threadIdx.x;
    if (i < GG * SCH * GF) g_pww[i] = to_tf32(pw_w[i]);
}

// ===========================================================================
// Kernel 0: offset conv as tf32 mma GEMM, FULLY hi/lo compensated:
//   acc += xh*wh + xl*wh + xh*wl   (xl*wl term ~2^-24, dropped)
// Offsets thus match the fp32 FFMA path to ~1e-7 -- critical because the
// bilinear clip at the border is DISCONTINUOUS in the offset.
// Tile 32x16 px = 512 rows (M), N=24 (18 used), K=288.
// ===========================================================================
#define OXT_F (18 * 34 * 20)      // 12240 floats per tile copy
#define WS2_F (288 * 24)          // 6912 floats per weight copy
#define OFF_SMEM_BYTES ((2 * OXT_F + 2 * WS2_F + 32) * 4)   // ~153 KB

__global__ __launch_bounds__(256) void k_offsets(
    const float* __restrict__ x,      // [B,H,W,64]
    const float* __restrict__ off_w,  // [G,3,3,32,18]
    const float* __restrict__ off_b)  // [G,18]
{
    extern __shared__ float sm0[];
    float* xt_hi = sm0;                  // [612 pos][20]
    float* xt_lo = sm0 + OXT_F;
    float* ws_hi = sm0 + 2 * OXT_F;      // [288][24]
    float* ws_lo = sm0 + 2 * OXT_F + WS2_F;
    float* wb    = sm0 + 2 * OXT_F + 2 * WS2_F;
    float* soff  = sm0;                  // alias (xt dead after k-loop)

    const int tid = threadIdx.x;
    const int z   = blockIdx.z;
    const int g   = z & 1;
    const int b   = z >> 1;
    const int ty0 = blockIdx.y * 16;
    const int tx0 = blockIdx.x * 32;

    // stage B = weights [k][j pad 24], split hi/lo (once)
    for (int i = tid; i < WS2_F; i += 256) {
        int k = i / 24, j = i % 24;
        int cch = k / 144, r = k % 144, t = r >> 4, c = r & 15;
        float v = 0.f;
        if (j < 18)
            v = off_w[(size_t)((g * 9 + t) * 32 + cch * 16 + c) * 18 + j];
        float hi = to_tf32(v);
        ws_hi[i] = hi;
        ws_lo[i] = v - hi;
    }
    if (tid < 18) wb[tid] = off_b[g * 18 + tid];

    const int warp = tid >> 5, lane = tid & 31;
    const int lg = lane >> 2, lt = lane & 3;

    float acc[4][3][4];
#pragma unroll
    for (int mt = 0; mt < 4; mt++)
#pragma unroll
        for (int jn = 0; jn < 3; jn++)
#pragma unroll
            for (int q = 0; q < 4; q++) acc[mt][jn][q] = 0.f;

    for (int cch = 0; cch < 2; cch++) {
        __syncthreads();
        // stage xt hi/lo: 18x34 positions x 16 ch
        for (int i = tid; i < 612 * 16; i += 256) {
            int pos = i >> 4, c = i & 15;
            int hy = ty0 + pos / 34 - 1, hx = tx0 + pos % 34 - 1;
            float v = 0.f;
            if (hy >= 0 && hy < HH && hx >= 0 && hx < WW)
                v = x[((size_t)((b * HH + hy) * WW + hx)) * CIN
                      + g * GCH + cch * 16 + c];
            float hi = to_tf32(v);
            xt_hi[pos * 20 + c] = hi;
            xt_lo[pos * 20 + c] = v - hi;
        }
        __syncthreads();

#pragma unroll 1
        for (int t = 0; t < 9; t++) {
            const int dy = t / 3, dx = t % 3;
#pragma unroll
            for (int half = 0; half < 2; half++) {
                const int kb = cch * 144 + t * 16 + half * 8;
                unsigned int bh[3][2], bl[3][2];
#pragma unroll
                for (int jn = 0; jn < 3; jn++) {
                    bh[jn][0] = *(const unsigned int*)&ws_hi[(kb + lt    ) * 24 + jn * 8 + lg];
                    bh[jn][1] = *(const unsigned int*)&ws_hi[(kb + lt + 4) * 24 + jn * 8 + lg];
                    bl[jn][0] = *(const unsigned int*)&ws_lo[(kb + lt    ) * 24 + jn * 8 + lg];
                    bl[jn][1] = *(const unsigned int*)&ws_lo[(kb + lt + 4) * 24 + jn * 8 + lg];
                }
#pragma unroll
                for (int mt = 0; mt < 4; mt++) {
                    const int p0  = warp * 64 + mt * 16;
                    const int py  = p0 >> 5, px0 = p0 & 31;
                    const int abase = ((py + dy) * 34 + px0 + dx) * 20 + half * 8;
                    const float* Ah = &xt_hi[abase];
                    const float* Al = &xt_lo[abase];
                    unsigned int h0 = *(const unsigned int*)&Ah[lg * 20 + lt];
                    unsigned int h1 = *(const unsigned int*)&Ah[(lg + 8) * 20 + lt];
                    unsigned int h2 = *(const unsigned int*)&Ah[lg * 20 + lt + 4];
                    unsigned int h3 = *(const unsigned int*)&Ah[(lg + 8) * 20 + lt + 4];
                    unsigned int l0 = *(const unsigned int*)&Al[lg * 20 + lt];
                    unsigned int l1 = *(const unsigned int*)&Al[(lg + 8) * 20 + lt];
                    unsigned int l2 = *(const unsigned int*)&Al[lg * 20 + lt + 4];
                    unsigned int l3 = *(const unsigned int*)&Al[(lg + 8) * 20 + lt + 4];
#pragma unroll
                    for (int jn = 0; jn < 3; jn++) {
                        mma_tf32(acc[mt][jn], h0, h1, h2, h3, bh[jn][0], bh[jn][1]);
                        mma_tf32(acc[mt][jn], l0, l1, l2, l3, bh[jn][0], bh[jn][1]);
                        mma_tf32(acc[mt][jn], h0, h1, h2, h3, bl[jn][0], bl[jn][1]);
                    }
                }
            }
        }
    }
    __syncthreads();   // xt dead -> soff

#pragma unroll
    for (int mt = 0; mt < 4; mt++) {
        const int p0 = warp * 64 + mt * 16;
#pragma unroll
        for (int jn = 0; jn < 3; jn++) {
            const int c0 = jn * 8 + 2 * lt;
            if (c0 < 18) {
                soff[(p0 + lg    ) * 18 + c0]     = acc[mt][jn][0] + wb[c0];
                soff[(p0 + lg    ) * 18 + c0 + 1] = acc[mt][jn][1] + wb[c0 + 1];
                soff[(p0 + lg + 8) * 18 + c0]     = acc[mt][jn][2] + wb[c0];
                soff[(p0 + lg + 8) * 18 + c0 + 1] = acc[mt][jn][3] + wb[c0 + 1];
            }
        }
    }
    __syncthreads();

    const size_t pbase = (size_t)b * (HH * WW) + (size_t)ty0 * WW + tx0;
    for (int i = tid; i < 32 * 16 * 18; i += 256) {
        int row = i / 576, rem = i % 576;
        g_off[((size_t)g * NP + pbase + (size_t)row * WW) * 18 + rem] = soff[i];
    }
}

// ===========================================================================
// Kernel 1: bilinear sampling (frozen; MLP-12 tap batching). fp16 output.
// ===========================================================================
__global__ __launch_bounds__(256) void k_sample(
    const float* __restrict__ x)
{
    const int tid  = threadIdx.x;
    const int g    = blockIdx.y;
    const int warp = tid >> 5, lane = tid & 31;
    const int p   = blockIdx.x * 8 + warp;
    const int b   = p >> 14;
    const int rem = p & 16383;
    const int yy  = rem >> 7;
    const int xx  = rem & 127;

    float offv = 0.f;
    if (lane < 18) offv = g_off[((size_t)g * NP + p) * 18 + lane];

    const float* xg = x + (size_t)b * (HH * WW) * CIN + g * GCH + lane;
    __half* outp = &g_samp16[((size_t)g * NP + p) * SCH + lane];

#pragma unroll
    for (int grp = 0; grp < 3; grp++) {
        float wa[3], wb_[3], wc[3], wd[3];
        int oa[3], ob[3], oc[3], od[3];
#pragma unroll
        for (int j = 0; j < 3; j++) {
            const int k = grp * 3 + j;
            float ox = __shfl_sync(0xffffffffu, offv, 2 * k);
            float oy = __shfl_sync(0xffffffffu, offv, 2 * k + 1);
            float lx = (float)xx + (float)(k % 3 - 1) + ox;
            float ly = (float)yy + (float)(k / 3 - 1) + oy;
            lx = fminf(fmaxf(lx, 0.f), 127.f);
            ly = fminf(fmaxf(ly, 0.f), 127.f);
            float x0f = fminf(fmaxf(floorf(lx), 0.f), 127.f);
            float y0f = fminf(fmaxf(floorf(ly), 0.f), 127.f);
            float x1f = fminf(x0f + 1.f, 127.f);
            float y1f = fminf(y0f + 1.f, 127.f);
            int x0 = (int)x0f, x1 = (int)x1f, y0 = (int)y0f, y1 = (int)y1f;
            float dx1 = x1f - lx, dx0 = lx - x0f;
            float dy1 = y1f - ly, dy0 = ly - y0f;
            oa[j] = (y0 * WW + x0) * CIN;
            ob[j] = (y1 * WW + x0) * CIN;
            oc[j] = (y0 * WW + x1) * CIN;
            od[j] = (y1 * WW + x1) * CIN;
            wa[j]  = dx1 * dy1;  wb_[j] = dx1 * dy0;
            wc[j]  = dx0 * dy1;  wd[j]  = dx0 * dy0;
        }
        float va[3], vb[3], vc[3], vd[3];
#pragma unroll
        for (int j = 0; j < 3; j++) {
            va[j] = __ldg(xg + oa[j]);
            vb[j] = __ldg(xg + ob[j]);
            vc[j] = __ldg(xg + oc[j]);
            vd[j] = __ldg(xg + od[j]);
        }
#pragma unroll
        for (int j = 0; j < 3; j++)
            outp[(grp * 3 + j) * 32] = __float2half_rn(
                wa[j]*va[j] + wb_[j]*vb[j] + wc[j]*vc[j] + wd[j]*vd[j]);
    }
}

// ===========================================================================
// Kernel 2: fused depthwise(3x3) + pointwise(288->64, tf32 mma).
// Round-10 validated version (226us, rel_err 3.58e-4) + LDS.64 dw v-loads.
// ===========================================================================
#define CHUNK  96
#define SM_HALO_H (100 * CHUNK)       // halves: 9600 (19200 B)
#define SM_HALO_F (SM_HALO_H / 2)     // float-equivalents: 4800
#define SM_Y    (64 * 100)            // 6400 floats
#define SM_PW   (96 * 72)             // 6912 floats
#define SM_DW   (9 * CHUNK)           // 864 floats
#define SM_BASE 200                   // 100 pointers (800 B)
#define SM_BYTES ((SM_HALO_F + SM_Y + SM_PW + SM_DW + SM_BASE + 8) * 4)
#define OUTP    68

__global__ __launch_bounds__(512, 2) void k_dwpw(
    const float* __restrict__ dw_w,   // [G,3,3,288,1]
    const float* __restrict__ dw_b,   // [G,288]
    const float* __restrict__ pw_b,   // [G,64]
    float* __restrict__ out)          // [B,H,W,128]
{
    extern __shared__ float smem[];
    __half* s_hal = (__half*)smem;                     // fp16 halo
    float* s_y    = smem + SM_HALO_F;
    float* s_pw   = smem + SM_HALO_F + SM_Y;
    float* s_dw   = smem + SM_HALO_F + SM_Y + SM_PW;
    const __half** s_base =
        (const __half**)(smem + SM_HALO_F + SM_Y + SM_PW + SM_DW + 8);
    float* s_red  = s_pw;                 // post-loop aliases
    float* s_out  = smem;                 // 64*68 floats < halo region

    const int tid = threadIdx.x;
    const int z   = blockIdx.z;
    const int gg  = z & 1;
    const int b   = z >> 1;
    const int ty0 = blockIdx.y * 8;
    const int tx0 = blockIdx.x * 8;

    const int warp = tid >> 5, lane = tid & 31;
    const int lg   = lane >> 2;
    const int lt   = lane & 3;
    const int team = warp >> 3;
    const int mtb  = (warp & 3) * 16;
    const int ntb  = ((warp >> 2) & 1) * 32;

    float acc[4][4];
#pragma unroll
    for (int j = 0; j < 4; j++)
#pragma unroll
        for (int q = 0; q < 4; q++) acc[j][q] = 0.f;

    float4* d4 = (float4*)s_dw;

    // --- halo base-pointer table (once per block) ---
    if (tid < 100) {
        int hy = ty0 + tid / 10 - 1, hx = tx0 + tid % 10 - 1;
        bool ok = (hy >= 0 && hy < HH && hx >= 0 && hx < WW);
        s_base[tid] = ok
            ? &g_samp16[((size_t)gg * NP + (size_t)((b * HH + hy) * WW + hx)) * SCH]
            : (const __half*)0;
    }
    __syncthreads();

    // warp-structured halo staging: no div/mod, 12 cpa16 per pixel
    auto stage_halo = [&](int cc) {
        const int cbase = cc * CHUNK;
        if (lane < 12) {
            for (int hp = warp; hp < 100; hp += 16) {
                const __half* base = s_base[hp];
                bool ok = (base != 0);
                const void* src = ok ? (const void*)(base + cbase + lane * 8)
                                     : (const void*)g_samp16;
                cpa16(&s_hal[hp * CHUNK + lane * 8], src, ok);
            }
        }
    };

    stage_halo(0);
    CPA_COMMIT();

    for (int cc = 0; cc < 3; cc++) {
        const int cbase = cc * CHUNK;
        __syncthreads();   // prev chunk's pw consumers done before restaging

        // stage dw weights + pre-rounded pw weights (async)
        for (int i = tid; i < 9 * 24; i += 512) {
            int t = i / 24, c4 = i % 24;
            cpa16(&s_dw[i * 4],
                  &dw_w[(size_t)gg * 2592 + t * SCH + cbase + c4 * 4], true);
        }
        for (int i = tid; i < 96 * 16; i += 512) {
            int c = i >> 4, f4 = i & 15;
            cpa16(&s_pw[c * 72 + f4 * 4],
                  &g_pww[((size_t)gg * SCH + cbase + c) * 64 + f4 * 4], true);
        }
        CPA_COMMIT();
        CPA_WAIT0();
        __syncthreads();

        // --- depthwise 3x3: strip of 4 px x 4 ch per thread (384 active) ---
        if (tid < 384) {
            const int strip = tid / 24, c4 = tid % 24;
            const int py = strip >> 1, qx0 = (strip & 1) * 4;
            float4 bias = __ldg((const float4*)&dw_b[gg * SCH + cbase + c4 * 4]);
            float a[4][4];
#pragma unroll
            for (int oxp = 0; oxp < 4; oxp++) {
                a[oxp][0] = bias.x; a[oxp][1] = bias.y;
                a[oxp][2] = bias.z; a[oxp][3] = bias.w;
            }
#pragma unroll
            for (int ty = 0; ty < 3; ty++) {
                const __half* hrow = &s_hal[((py + ty) * 10 + qx0) * CHUNK + c4 * 4];
                float vv[6][4];
#pragma unroll
                for (int i = 0; i < 6; i++) {
                    uint2 u = *(const uint2*)&hrow[i * CHUNK];
                    float2 f01 = __half22float2(*(__half2*)&u.x);
                    float2 f23 = __half22float2(*(__half2*)&u.y);
                    vv[i][0] = f01.x; vv[i][1] = f01.y;
                    vv[i][2] = f23.x; vv[i][3] = f23.y;
                }
#pragma unroll
                for (int tx = 0; tx < 3; tx++) {
                    float4 w = d4[(ty * 3 + tx) * 24 + c4];
#pragma unroll
                    for (int oxp = 0; oxp < 4; oxp++) {
                        a[oxp][0] = fmaf(w.x, vv[oxp + tx][0], a[oxp][0]);
                        a[oxp][1] = fmaf(w.y, vv[oxp + tx][1], a[oxp][1]);
                        a[oxp][2] = fmaf(w.z, vv[oxp + tx][2], a[oxp][2]);
                        a[oxp][3] = fmaf(w.w, vv[oxp + tx][3], a[oxp][3]);
                    }
                }
            }
#pragma unroll
            for (int oxp = 0; oxp < 4; oxp++) {
                float4 r = make_float4(to_tf32(a[oxp][0]), to_tf32(a[oxp][1]),
                                       to_tf32(a[oxp][2]), to_tf32(a[oxp][3]));
                *(float4*)&s_y[(py * 8 + qx0 + oxp) * 100 + c4 * 4] = r;
            }
        }
        __syncthreads();   // y ready; halo dead

        if (cc < 2) {
            stage_halo(cc + 1);
            CPA_COMMIT();
        }

        // --- pointwise via tf32 mma: this team's 48-channel K slice ---
#pragma unroll
        for (int s = 0; s < 6; s++) {
            const int k0 = team * 48 + s * 8;
            const unsigned int* yA =
                (const unsigned int*)&s_y[(mtb + lg) * 100 + k0 + lt];
            unsigned int a0 = yA[0],   a1 = yA[800];
            unsigned int a2 = yA[4],   a3 = yA[804];
#pragma unroll
            for (int j = 0; j < 4; j++) {
                unsigned int b0 = *(const unsigned int*)
                    &s_pw[(k0 + lt    ) * 72 + ntb + j * 8 + lg];
                unsigned int b1 = *(const unsigned int*)
                    &s_pw[(k0 + lt + 4) * 72 + ntb + j * 8 + lg];
                mma_tf32(acc[j], a0, a1, a2, a3, b0, b1);
            }
        }
    }
    __syncthreads();

    // split-K reduce across teams
    if (team == 1) {
        float* dst = &s_red[((warp & 7) * 32 + lane) * 16];
#pragma unroll
        for (int j = 0; j < 4; j++)
#pragma unroll
            for (int q = 0; q < 4; q++) dst[j * 4 + q] = acc[j][q];
    }
    __syncthreads();
    if (team == 0) {
        const float* src = &s_red[((warp & 7) * 32 + lane) * 16];
        const int px0 = mtb + lg, px1 = mtb + lg + 8;
#pragma unroll
        for (int j = 0; j < 4; j++) {
            int f0 = ntb + j * 8 + 2 * lt;
            float b0v = __ldg(&pw_b[gg * GF + f0]);
            float b1v = __ldg(&pw_b[gg * GF + f0 + 1]);
            s_out[px0 * OUTP + f0]     = acc[j][0] + src[j*4+0] + b0v;
            s_out[px0 * OUTP + f0 + 1] = acc[j][1] + src[j*4+1] + b1v;
            s_out[px1 * OUTP + f0]     = acc[j][2] + src[j*4+2] + b0v;
            s_out[px1 * OUTP + f0 + 1] = acc[j][3] + src[j*4+3] + b1v;
        }
    }
    __syncthreads();

    for (int i = tid; i < 4096; i += 512) {
        int p = i >> 6, f = i & 63;
        int py = p >> 3, px = p & 7;
        out[((size_t)((b * HH + ty0 + py) * WW) + tx0 + px) * (GG * GF)
            + gg * GF + f] = s_out[p * OUTP + f];
    }
}

// ---------------------------------------------------------------------------
extern "C" void kernel_launch(void* const* d_in, const int* in_sizes, int n_in,
                              void* d_out, int out_size)
{
    const float* x     = (const float*)d_in[0];
    const float* off_w = (const float*)d_in[1];
    const float* off_b = (const float*)d_in[2];
    const float* dw_w  = (const float*)d_in[3];
    const float* dw_b  = (const float*)d_in[4];
    const float* pw_w  = (const float*)d_in[5];
    const float* pw_b  = (const float*)d_in[6];
    float* out = (float*)d_out;

    cudaFuncSetAttribute(k_offsets, cudaFuncAttributeMaxDynamicSharedMemorySize,
                         OFF_SMEM_BYTES);
    cudaFuncSetAttribute(k_dwpw, cudaFuncAttributeMaxDynamicSharedMemorySize,
                         SM_BYTES);

    k_prep<<<(GG * SCH * GF + 255) / 256, 256>>>(pw_w);
    k_offsets<<<dim3(WW/32, HH/16, BB*GG), 256, OFF_SMEM_BYTES>>>(x, off_w, off_b);
    k_sample<<<dim3(NP / 8, GG), 256>>>(x);
    k_dwpw<<<dim3(WW / 8, HH / 8, BB * GG), 512, SM_BYTES>>>(
        dw_w, dw_b, pw_b, out);
}